// round 11
// baseline (speedup 1.0000x reference)
#include <cuda_runtime.h>

#define BB 512
#define TT 1024
#define IDIM 64
#define HH 10
#define G4 40   // 4*H

typedef unsigned long long u64;

// Scratch (static device globals — no runtime allocation)
// XG layout per row: unit-interleaved pairs, u64 index p2 (0..19):
//   p2 = 2k   -> (i_k, f_k) preacts, PRE-SCALED by 0.5
//   p2 = 2k+1 -> (g_k, o_k) preacts, g unscaled, o PRE-SCALED by 0.5
__device__ float d_XG1[BB * TT * G4];
__device__ float d_XG2[BB * TT * G4];
__device__ float d_h1T[BB * HH];   // stores hbig = 2*h
__device__ float d_c1T[BB * HH];

// position p = 4*u + gt (gt: 0=i,1=f,2=g,3=o) -> original PyTorch gate row
__device__ __forceinline__ int old_gate(int p) {
    int u = p >> 2, gt = p & 3;
    return gt * HH + u;
}

__device__ __forceinline__ float tanh_ap(float x) {
    float y;
    asm("tanh.approx.f32 %0, %1;" : "=f"(y) : "f"(x));
    return y;
}

// ---- packed f32x2 helpers (sm_100+) ----
__device__ __forceinline__ u64 pk2(float lo, float hi) {
    u64 r; asm("mov.b64 %0, {%1, %2};" : "=l"(r) : "f"(lo), "f"(hi)); return r;
}
__device__ __forceinline__ void upk2(float& lo, float& hi, u64 v) {
    asm("mov.b64 {%0, %1}, %2;" : "=f"(lo), "=f"(hi) : "l"(v));
}
__device__ __forceinline__ u64 fma2(u64 a, u64 b, u64 c) {
    u64 d; asm("fma.rn.f32x2 %0, %1, %2, %3;" : "=l"(d) : "l"(a), "l"(b), "l"(c)); return d;
}
__device__ __forceinline__ u64 mul2(u64 a, u64 b) {
    u64 d; asm("mul.rn.f32x2 %0, %1, %2;" : "=l"(d) : "l"(a), "l"(b)); return d;
}
__device__ __forceinline__ u64 add2(u64 a, u64 b) {
    u64 d; asm("add.rn.f32x2 %0, %1, %2;" : "=l"(d) : "l"(a), "l"(b)); return d;
}

// ---------------------------------------------------------------------------
// K1 (unchanged — measured 98us): input GEMM -> d_XG1, folded scales.
// ---------------------------------------------------------------------------
__global__ __launch_bounds__(256) void k_inputgemm(
    const float* __restrict__ x,      // [B*T, 64]
    const float* __restrict__ W,      // [40, 64] (orig gate order)
    const float* __restrict__ b1,
    const float* __restrict__ b2)
{
    __shared__ u64 sW[64 * 20];
    __shared__ u64 sB[20];
    int tid = threadIdx.x;
    for (int e = tid; e < 64 * 20; e += 256) {
        int k = e / 20, p2 = e % 20;
        float slo = (p2 & 1) ? 1.0f : 0.5f;
        float lo = slo * W[old_gate(2 * p2) * 64 + k];
        float hi = 0.5f * W[old_gate(2 * p2 + 1) * 64 + k];
        sW[e] = pk2(lo, hi);
    }
    for (int e = tid; e < 20; e += 256) {
        int p2 = e;
        float slo = (p2 & 1) ? 1.0f : 0.5f;
        int oA = old_gate(2 * p2), oB = old_gate(2 * p2 + 1);
        sB[e] = pk2(slo * (b1[oA] + b2[oA]), 0.5f * (b1[oB] + b2[oB]));
    }
    __syncthreads();

    int gt = blockIdx.x * 256 + tid;
    int rowblk = gt >> 2;
    int q = gt & 3;
    size_t r0 = (size_t)rowblk * 8;

    u64 acc[8][5];
#pragma unroll
    for (int r = 0; r < 8; r++)
#pragma unroll
        for (int j = 0; j < 5; j++) acc[r][j] = sB[q + 4 * j];

    const float4* x4 = reinterpret_cast<const float4*>(x);
#pragma unroll 2
    for (int kk = 0; kk < 16; kk++) {
        float4 xv[8];
#pragma unroll
        for (int r = 0; r < 8; r++) xv[r] = x4[(r0 + r) * 16 + kk];
#pragma unroll
        for (int c = 0; c < 4; c++) {
            u64 xd[8];
#pragma unroll
            for (int r = 0; r < 8; r++) {
                float xc = (c == 0) ? xv[r].x : (c == 1) ? xv[r].y
                         : (c == 2) ? xv[r].z : xv[r].w;
                xd[r] = pk2(xc, xc);
            }
#pragma unroll
            for (int j = 0; j < 5; j++) {
                u64 w = sW[(4 * kk + c) * 20 + q + 4 * j];
#pragma unroll
                for (int r = 0; r < 8; r++)
                    acc[r][j] = fma2(w, xd[r], acc[r][j]);
            }
        }
    }
#pragma unroll
    for (int r = 0; r < 8; r++) {
        u64* orow = reinterpret_cast<u64*>(d_XG1 + (r0 + r) * G4);
#pragma unroll
        for (int j = 0; j < 5; j++) orow[q + 4 * j] = acc[r][j];
    }
}

// ---------------------------------------------------------------------------
// lstm1 step: role-shared trees.
//   lanes 0-9  (gate role): wa/wb = layer-1 Whh; tree base = xg1[t]
//   lanes 10-19 (gemm role): wa/wb = layer-2 Wih2; tree base = bias
// The shared tree consumes hv = h1[t-1]:
//   gate lanes  -> gates(t)   (correct)
//   gemm lanes  -> xg2[t-1]   -> STORED AT INDEX t-1 (guard t>=1)
// One tail gemm after the loop produces xg2[TT-1].
// Weights pre-scaled (0.25,0.25)/(0.5,0.25); hbig = 2h convention.
// ---------------------------------------------------------------------------
#define STEP1(hb, cc, hv, ab, outp, sidx)                                     \
    {                                                                         \
        u64 t1 = gemmrole ? bIF : (ab).x;                                     \
        u64 t2 = gemmrole ? bGO : (ab).y;                                     \
        u64 e1 = fma2(wa[0], hv[0], t1);                                      \
        e1 = fma2(wa[2], hv[2], e1);                                          \
        e1 = fma2(wa[4], hv[4], e1);                                          \
        e1 = fma2(wa[6], hv[6], e1);                                          \
        e1 = fma2(wa[8], hv[8], e1);                                          \
        u64 o1 = mul2(wa[1], hv[1]);                                          \
        o1 = fma2(wa[3], hv[3], o1);                                          \
        o1 = fma2(wa[5], hv[5], o1);                                          \
        o1 = fma2(wa[7], hv[7], o1);                                          \
        o1 = fma2(wa[9], hv[9], o1);                                          \
        u64 g1 = add2(e1, o1);                                                \
        u64 e2 = fma2(wb[0], hv[0], t2);                                      \
        e2 = fma2(wb[2], hv[2], e2);                                          \
        e2 = fma2(wb[4], hv[4], e2);                                          \
        e2 = fma2(wb[6], hv[6], e2);                                          \
        e2 = fma2(wb[8], hv[8], e2);                                          \
        u64 o2 = mul2(wb[1], hv[1]);                                          \
        o2 = fma2(wb[3], hv[3], o2);                                          \
        o2 = fma2(wb[5], hv[5], o2);                                          \
        o2 = fma2(wb[7], hv[7], o2);                                          \
        o2 = fma2(wb[9], hv[9], o2);                                          \
        u64 g2 = add2(e2, o2);                                                \
        if (gemmrole && (sidx) >= 0) {                                        \
            ulonglong2 v; v.x = g1; v.y = g2;                                 \
            (outp)[(size_t)(sidx) * HH] = v;                                  \
        }                                                                     \
        float xi, xf, xg, xo;                                                 \
        upk2(xi, xf, g1);                                                     \
        upk2(xg, xo, g2);                                                     \
        float ti = tanh_ap(xi);                                               \
        float tf = tanh_ap(xf);                                               \
        float tg = tanh_ap(xg);                                               \
        float to_ = tanh_ap(xo);                                              \
        float u_ = fmaf(tf, cc, cc);                                          \
        float v_ = fmaf(ti, tg, tg);                                          \
        cc = 0.5f * (u_ + v_);                                                \
        float tc = tanh_ap(cc);                                               \
        hb = fmaf(to_, tc, tc);                                               \
        _Pragma("unroll")                                                     \
        for (int j = 0; j < 10; j++) {                                        \
            float hj = __shfl_sync(0xffffffffu, hb, j);                       \
            hv[j] = pk2(hj, hj);                                              \
        }                                                                     \
    }

// Tail gemm: one evaluation of the gemm tree with the FINAL hv (= h1[TT-1]),
// stored at index TT-1. Gate lanes compute garbage, store is guarded.
#define GEMM_TAIL(hv, outp)                                                   \
    {                                                                         \
        u64 e1 = fma2(wa[0], hv[0], bIF);                                     \
        e1 = fma2(wa[2], hv[2], e1);                                          \
        e1 = fma2(wa[4], hv[4], e1);                                          \
        e1 = fma2(wa[6], hv[6], e1);                                          \
        e1 = fma2(wa[8], hv[8], e1);                                          \
        u64 o1 = mul2(wa[1], hv[1]);                                          \
        o1 = fma2(wa[3], hv[3], o1);                                          \
        o1 = fma2(wa[5], hv[5], o1);                                          \
        o1 = fma2(wa[7], hv[7], o1);                                          \
        o1 = fma2(wa[9], hv[9], o1);                                          \
        u64 g1 = add2(e1, o1);                                                \
        u64 e2 = fma2(wb[0], hv[0], bGO);                                     \
        e2 = fma2(wb[2], hv[2], e2);                                          \
        e2 = fma2(wb[4], hv[4], e2);                                          \
        e2 = fma2(wb[6], hv[6], e2);                                          \
        e2 = fma2(wb[8], hv[8], e2);                                          \
        u64 o2 = mul2(wb[1], hv[1]);                                          \
        o2 = fma2(wb[3], hv[3], o2);                                          \
        o2 = fma2(wb[5], hv[5], o2);                                          \
        o2 = fma2(wb[7], hv[7], o2);                                          \
        o2 = fma2(wb[9], hv[9], o2);                                          \
        u64 g2 = add2(e2, o2);                                                \
        if (gemmrole) {                                                       \
            ulonglong2 v; v.x = g1; v.y = g2;                                 \
            (outp)[(size_t)(TT - 1) * HH] = v;                                \
        }                                                                     \
    }

__global__ __launch_bounds__(128) void k_lstm1(
    const float* __restrict__ Whh,    // [40,10] layer-1
    const float* __restrict__ h0,
    const float* __restrict__ c0,
    const float* __restrict__ Wih2,   // [40,10]
    const float* __restrict__ bih2,
    const float* __restrict__ bhh2)
{
    int warp = (blockIdx.x * blockDim.x + threadIdx.x) >> 5;  // 256 warps
    int lane = threadIdx.x & 31;
    int k2 = lane % HH;
    bool gemmrole = (lane >= 10 && lane < 20);
    bool klow = lane < HH;

    const float* Wsel = gemmrole ? Wih2 : Whh;
    u64 wa[10], wb[10];
#pragma unroll
    for (int j = 0; j < 10; j++) {
        wa[j] = pk2(0.25f * Wsel[(0 * HH + k2) * HH + j],
                    0.25f * Wsel[(1 * HH + k2) * HH + j]);
        wb[j] = pk2(0.50f * Wsel[(2 * HH + k2) * HH + j],
                    0.25f * Wsel[(3 * HH + k2) * HH + j]);
    }
    u64 bIF = pk2(0.5f * (bih2[0 * HH + k2] + bhh2[0 * HH + k2]),
                  0.5f * (bih2[1 * HH + k2] + bhh2[1 * HH + k2]));
    u64 bGO = pk2(1.0f * (bih2[2 * HH + k2] + bhh2[2 * HH + k2]),
                  0.5f * (bih2[3 * HH + k2] + bhh2[3 * HH + k2]));

    int bA = 2 * warp, bB = 2 * warp + 1;
    float hbA = 2.0f * h0[bA * HH + k2], ccA = c0[bA * HH + k2];
    float hbB = 2.0f * h0[bB * HH + k2], ccB = c0[bB * HH + k2];
    u64 hvA[10], hvB[10];
#pragma unroll
    for (int j = 0; j < 10; j++) {
        float ha = __shfl_sync(0xffffffffu, hbA, j);
        float hbv = __shfl_sync(0xffffffffu, hbB, j);
        hvA[j] = pk2(ha, ha);
        hvB[j] = pk2(hbv, hbv);
    }

    const ulonglong2* baseA =
        reinterpret_cast<const ulonglong2*>(d_XG1) + (size_t)bA * TT * HH + k2;
    const ulonglong2* baseB =
        reinterpret_cast<const ulonglong2*>(d_XG1) + (size_t)bB * TT * HH + k2;
    ulonglong2* outA =
        reinterpret_cast<ulonglong2*>(d_XG2) + (size_t)bA * TT * HH + k2;
    ulonglong2* outB =
        reinterpret_cast<ulonglong2*>(d_XG2) + (size_t)bB * TT * HH + k2;

    ulonglong2 cA = baseA[0], cB = baseB[0];
    ulonglong2 nA = baseA[HH], nB = baseB[HH];

    for (int t = 0; t < TT; t++) {
        // shared tree consumes hv = h1[t-1] -> gemm output is xg2[t-1]
        STEP1(hbA, ccA, hvA, cA, outA, t - 1);
        STEP1(hbB, ccB, hvB, cB, outB, t - 1);
        cA = nA; cB = nB;
        if (t + 2 < TT) {
            nA = baseA[(size_t)(t + 2) * HH];
            nB = baseB[(size_t)(t + 2) * HH];
        }
    }
    // final gemm with hv = h1[TT-1] -> xg2[TT-1]
    GEMM_TAIL(hvA, outA);
    GEMM_TAIL(hvB, outB);

    if (klow) {
        d_h1T[bA * HH + k2] = hbA;
        d_c1T[bA * HH + k2] = ccA;
        d_h1T[bB * HH + k2] = hbB;
        d_c1T[bB * HH + k2] = ccB;
    }
}

// ---------------------------------------------------------------------------
// lstm2 step: plain recurrence, dual chains per warp.
// ---------------------------------------------------------------------------
#define STEP2(hb, cc, hv, ab)                                                 \
    {                                                                         \
        u64 e1 = fma2(wa[0], hv[0], (ab).x);                                  \
        e1 = fma2(wa[2], hv[2], e1);                                          \
        e1 = fma2(wa[4], hv[4], e1);                                          \
        e1 = fma2(wa[6], hv[6], e1);                                          \
        e1 = fma2(wa[8], hv[8], e1);                                          \
        u64 o1 = mul2(wa[1], hv[1]);                                          \
        o1 = fma2(wa[3], hv[3], o1);                                          \
        o1 = fma2(wa[5], hv[5], o1);                                          \
        o1 = fma2(wa[7], hv[7], o1);                                          \
        o1 = fma2(wa[9], hv[9], o1);                                          \
        u64 g1 = add2(e1, o1);                                                \
        u64 e2 = fma2(wb[0], hv[0], (ab).y);                                  \
        e2 = fma2(wb[2], hv[2], e2);                                          \
        e2 = fma2(wb[4], hv[4], e2);                                          \
        e2 = fma2(wb[6], hv[6], e2);                                          \
        e2 = fma2(wb[8], hv[8], e2);                                          \
        u64 o2 = mul2(wb[1], hv[1]);                                          \
        o2 = fma2(wb[3], hv[3], o2);                                          \
        o2 = fma2(wb[5], hv[5], o2);                                          \
        o2 = fma2(wb[7], hv[7], o2);                                          \
        o2 = fma2(wb[9], hv[9], o2);                                          \
        u64 g2 = add2(e2, o2);                                                \
        float xi, xf, xg, xo;                                                 \
        upk2(xi, xf, g1);                                                     \
        upk2(xg, xo, g2);                                                     \
        float ti = tanh_ap(xi);                                               \
        float tf = tanh_ap(xf);                                               \
        float tg = tanh_ap(xg);                                               \
        float to_ = tanh_ap(xo);                                              \
        float u_ = fmaf(tf, cc, cc);                                          \
        float v_ = fmaf(ti, tg, tg);                                          \
        cc = 0.5f * (u_ + v_);                                                \
        float tc = tanh_ap(cc);                                               \
        hb = fmaf(to_, tc, tc);                                               \
        _Pragma("unroll")                                                     \
        for (int j = 0; j < 10; j++) {                                        \
            float hj = __shfl_sync(0xffffffffu, hb, j);                       \
            hv[j] = pk2(hj, hj);                                              \
        }                                                                     \
    }

__global__ __launch_bounds__(128) void k_lstm2(
    const float* __restrict__ Whh,    // [40,10] layer-2
    const float* __restrict__ fc1w,
    const float* __restrict__ fc1b,
    const float* __restrict__ fc2w,   // [1024]
    const float* __restrict__ fc2b,
    float* __restrict__ out)
{
    int warp = (blockIdx.x * blockDim.x + threadIdx.x) >> 5;  // 256 warps
    int lane = threadIdx.x & 31;
    int k2 = lane % HH;
    bool klow = lane < HH;

    u64 wa[10], wb[10];
#pragma unroll
    for (int j = 0; j < 10; j++) {
        wa[j] = pk2(0.25f * Whh[(0 * HH + k2) * HH + j],
                    0.25f * Whh[(1 * HH + k2) * HH + j]);
        wb[j] = pk2(0.50f * Whh[(2 * HH + k2) * HH + j],
                    0.25f * Whh[(3 * HH + k2) * HH + j]);
    }

    int bA = 2 * warp, bB = 2 * warp + 1;
    float hbA = d_h1T[bA * HH + k2], ccA = d_c1T[bA * HH + k2];
    float hbB = d_h1T[bB * HH + k2], ccB = d_c1T[bB * HH + k2];
    u64 hvA[10], hvB[10];
#pragma unroll
    for (int j = 0; j < 10; j++) {
        float ha = __shfl_sync(0xffffffffu, hbA, j);
        float hbv = __shfl_sync(0xffffffffu, hbB, j);
        hvA[j] = pk2(ha, ha);
        hvB[j] = pk2(hbv, hbv);
    }

    const ulonglong2* baseA =
        reinterpret_cast<const ulonglong2*>(d_XG2) + (size_t)bA * TT * HH + k2;
    const ulonglong2* baseB =
        reinterpret_cast<const ulonglong2*>(d_XG2) + (size_t)bB * TT * HH + k2;

    ulonglong2 cA = baseA[0], cB = baseB[0];
    ulonglong2 nA = baseA[HH], nB = baseB[HH];

    float accA = 0.0f, accB = 0.0f;   // sum_t hbig * fc2w[t]
    float s2 = 0.0f;                  // sum_t fc2w[t]

    for (int t = 0; t < TT; t++) {
        float fw = __ldg(fc2w + t);
        STEP2(hbA, ccA, hvA, cA);
        accA = fmaf(hbA, fw, accA);
        STEP2(hbB, ccB, hvB, cB);
        accB = fmaf(hbB, fw, accB);
        s2 += fw;
        cA = nA; cB = nB;
        if (t + 2 < TT) {
            nA = baseA[(size_t)(t + 2) * HH];
            nB = baseB[(size_t)(t + 2) * HH];
        }
    }

    // acc holds 2*sum(h*fw) -> scale fc1w by 0.5; lanes >=10 contribute 0.
    float fscale = klow ? 0.5f * fc1w[k2] : 0.0f;
    float vA = accA * fscale;
    float vB = accB * fscale;
#pragma unroll
    for (int off = 16; off > 0; off >>= 1) {
        vA += __shfl_xor_sync(0xffffffffu, vA, off);
        vB += __shfl_xor_sync(0xffffffffu, vB, off);
    }
    if (lane == 0) {
        float tail = fc1b[0] * s2 + fc2b[0];
        out[bA] = vA + tail;
        out[bB] = vB + tail;
    }
}

// ---------------------------------------------------------------------------
extern "C" void kernel_launch(void* const* d_in, const int* in_sizes, int n_in,
                              void* d_out, int out_size)
{
    const float* x    = (const float*)d_in[0];
    const float* h0   = (const float*)d_in[1];
    const float* c0   = (const float*)d_in[2];
    const float* Wih1 = (const float*)d_in[3];
    const float* Whh1 = (const float*)d_in[4];
    const float* bih1 = (const float*)d_in[5];
    const float* bhh1 = (const float*)d_in[6];
    const float* Wih2 = (const float*)d_in[7];
    const float* Whh2 = (const float*)d_in[8];
    const float* bih2 = (const float*)d_in[9];
    const float* bhh2 = (const float*)d_in[10];
    const float* fc1w = (const float*)d_in[11];
    const float* fc1b = (const float*)d_in[12];
    const float* fc2w = (const float*)d_in[13];
    const float* fc2b = (const float*)d_in[14];
    float* out = (float*)d_out;

    k_inputgemm<<<1024, 256>>>(x, Wih1, bih1, bhh1);       // 8 rows/thread (98us)
    k_lstm1<<<64, 128>>>(Whh1, h0, c0, Wih2, bih2, bhh2);  // role-shared tree + dual chains
    k_lstm2<<<64, 128>>>(Whh2, fc1w, fc1b, fc2w, fc2b, out);
}

// round 12
// speedup vs baseline: 2.9695x; 2.9695x over previous
#include <cuda_runtime.h>

#define BB 512
#define TT 1024
#define IDIM 64
#define HH 10
#define G4 40   // 4*H

typedef unsigned long long u64;

// Scratch (static device globals — no runtime allocation)
// XG layout per row: unit-interleaved pairs, u64 index p2 (0..19):
//   p2 = 2k   -> (i_k, f_k) preacts, PRE-SCALED by 0.5
//   p2 = 2k+1 -> (g_k, o_k) preacts, g unscaled, o PRE-SCALED by 0.5
__device__ float d_XG1[BB * TT * G4];
__device__ float d_XG2[BB * TT * G4];
__device__ float d_h1T[BB * HH];   // stores hbig = 2*h
__device__ float d_c1T[BB * HH];

// position p = 4*u + gt (gt: 0=i,1=f,2=g,3=o) -> original PyTorch gate row
__device__ __forceinline__ int old_gate(int p) {
    int u = p >> 2, gt = p & 3;
    return gt * HH + u;
}

__device__ __forceinline__ float tanh_ap(float x) {
    float y;
    asm("tanh.approx.f32 %0, %1;" : "=f"(y) : "f"(x));
    return y;
}

// ---- packed f32x2 helpers (sm_100+) ----
__device__ __forceinline__ u64 pk2(float lo, float hi) {
    u64 r; asm("mov.b64 %0, {%1, %2};" : "=l"(r) : "f"(lo), "f"(hi)); return r;
}
__device__ __forceinline__ void upk2(float& lo, float& hi, u64 v) {
    asm("mov.b64 {%0, %1}, %2;" : "=f"(lo), "=f"(hi) : "l"(v));
}
__device__ __forceinline__ u64 fma2(u64 a, u64 b, u64 c) {
    u64 d; asm("fma.rn.f32x2 %0, %1, %2, %3;" : "=l"(d) : "l"(a), "l"(b), "l"(c)); return d;
}
__device__ __forceinline__ u64 mul2(u64 a, u64 b) {
    u64 d; asm("mul.rn.f32x2 %0, %1, %2;" : "=l"(d) : "l"(a), "l"(b)); return d;
}
__device__ __forceinline__ u64 add2(u64 a, u64 b) {
    u64 d; asm("add.rn.f32x2 %0, %1, %2;" : "=l"(d) : "l"(a), "l"(b)); return d;
}

// ---------------------------------------------------------------------------
// K1 (unchanged — measured 98us): input GEMM -> d_XG1, folded scales.
// ---------------------------------------------------------------------------
__global__ __launch_bounds__(256) void k_inputgemm(
    const float* __restrict__ x,      // [B*T, 64]
    const float* __restrict__ W,      // [40, 64] (orig gate order)
    const float* __restrict__ b1,
    const float* __restrict__ b2)
{
    __shared__ u64 sW[64 * 20];
    __shared__ u64 sB[20];
    int tid = threadIdx.x;
    for (int e = tid; e < 64 * 20; e += 256) {
        int k = e / 20, p2 = e % 20;
        float slo = (p2 & 1) ? 1.0f : 0.5f;
        float lo = slo * W[old_gate(2 * p2) * 64 + k];
        float hi = 0.5f * W[old_gate(2 * p2 + 1) * 64 + k];
        sW[e] = pk2(lo, hi);
    }
    for (int e = tid; e < 20; e += 256) {
        int p2 = e;
        float slo = (p2 & 1) ? 1.0f : 0.5f;
        int oA = old_gate(2 * p2), oB = old_gate(2 * p2 + 1);
        sB[e] = pk2(slo * (b1[oA] + b2[oA]), 0.5f * (b1[oB] + b2[oB]));
    }
    __syncthreads();

    int gt = blockIdx.x * 256 + tid;
    int rowblk = gt >> 2;
    int q = gt & 3;
    size_t r0 = (size_t)rowblk * 8;

    u64 acc[8][5];
#pragma unroll
    for (int r = 0; r < 8; r++)
#pragma unroll
        for (int j = 0; j < 5; j++) acc[r][j] = sB[q + 4 * j];

    const float4* x4 = reinterpret_cast<const float4*>(x);
#pragma unroll 2
    for (int kk = 0; kk < 16; kk++) {
        float4 xv[8];
#pragma unroll
        for (int r = 0; r < 8; r++) xv[r] = x4[(r0 + r) * 16 + kk];
#pragma unroll
        for (int c = 0; c < 4; c++) {
            u64 xd[8];
#pragma unroll
            for (int r = 0; r < 8; r++) {
                float xc = (c == 0) ? xv[r].x : (c == 1) ? xv[r].y
                         : (c == 2) ? xv[r].z : xv[r].w;
                xd[r] = pk2(xc, xc);
            }
#pragma unroll
            for (int j = 0; j < 5; j++) {
                u64 w = sW[(4 * kk + c) * 20 + q + 4 * j];
#pragma unroll
                for (int r = 0; r < 8; r++)
                    acc[r][j] = fma2(w, xd[r], acc[r][j]);
            }
        }
    }
#pragma unroll
    for (int r = 0; r < 8; r++) {
        u64* orow = reinterpret_cast<u64*>(d_XG1 + (r0 + r) * G4);
#pragma unroll
        for (int j = 0; j < 5; j++) orow[q + 4 * j] = acc[r][j];
    }
}

// ---------------------------------------------------------------------------
// lstm1 step: role-shared trees (validated correct in R11), SINGLE chain.
//   lanes 0-9  (gate role): wa/wb = layer-1 Whh; tree base = xg1[t]
//   lanes 10-19 (gemm role): wa/wb = layer-2 Wih2; tree base = bias
// Shared tree consumes hv = h1[t-1]: gate lanes -> gates(t); gemm lanes ->
// xg2[t-1], stored at index t-1 (sidx guard). Tail produces xg2[TT-1].
// Weights pre-scaled (0.25,0.25)/(0.5,0.25); hbig = 2h convention.
// ---------------------------------------------------------------------------
#define STEP1(hb, cc, hv, ab, outp, sidx)                                     \
    {                                                                         \
        u64 t1 = gemmrole ? bIF : (ab).x;                                     \
        u64 t2 = gemmrole ? bGO : (ab).y;                                     \
        u64 e1 = fma2(wa[0], hv[0], t1);                                      \
        e1 = fma2(wa[2], hv[2], e1);                                          \
        e1 = fma2(wa[4], hv[4], e1);                                          \
        e1 = fma2(wa[6], hv[6], e1);                                          \
        e1 = fma2(wa[8], hv[8], e1);                                          \
        u64 o1 = mul2(wa[1], hv[1]);                                          \
        o1 = fma2(wa[3], hv[3], o1);                                          \
        o1 = fma2(wa[5], hv[5], o1);                                          \
        o1 = fma2(wa[7], hv[7], o1);                                          \
        o1 = fma2(wa[9], hv[9], o1);                                          \
        u64 g1 = add2(e1, o1);                                                \
        u64 e2 = fma2(wb[0], hv[0], t2);                                      \
        e2 = fma2(wb[2], hv[2], e2);                                          \
        e2 = fma2(wb[4], hv[4], e2);                                          \
        e2 = fma2(wb[6], hv[6], e2);                                          \
        e2 = fma2(wb[8], hv[8], e2);                                          \
        u64 o2 = mul2(wb[1], hv[1]);                                          \
        o2 = fma2(wb[3], hv[3], o2);                                          \
        o2 = fma2(wb[5], hv[5], o2);                                          \
        o2 = fma2(wb[7], hv[7], o2);                                          \
        o2 = fma2(wb[9], hv[9], o2);                                          \
        u64 g2 = add2(e2, o2);                                                \
        if (gemmrole && (sidx) >= 0) {                                        \
            ulonglong2 v; v.x = g1; v.y = g2;                                 \
            (outp)[(size_t)(sidx) * HH] = v;                                  \
        }                                                                     \
        float xi, xf, xg, xo;                                                 \
        upk2(xi, xf, g1);                                                     \
        upk2(xg, xo, g2);                                                     \
        float ti = tanh_ap(xi);                                               \
        float tf = tanh_ap(xf);                                               \
        float tg = tanh_ap(xg);                                               \
        float to_ = tanh_ap(xo);                                              \
        float u_ = fmaf(tf, cc, cc);                                          \
        float v_ = fmaf(ti, tg, tg);                                          \
        cc = 0.5f * (u_ + v_);                                                \
        float tc = tanh_ap(cc);                                               \
        hb = fmaf(to_, tc, tc);                                               \
        _Pragma("unroll")                                                     \
        for (int j = 0; j < 10; j++) {                                        \
            float hj = __shfl_sync(0xffffffffu, hb, j);                       \
            hv[j] = pk2(hj, hj);                                              \
        }                                                                     \
    }

// Tail gemm: one evaluation with the FINAL hv (= h1[TT-1]) -> xg2[TT-1].
#define GEMM_TAIL(hv, outp)                                                   \
    {                                                                         \
        u64 e1 = fma2(wa[0], hv[0], bIF);                                     \
        e1 = fma2(wa[2], hv[2], e1);                                          \
        e1 = fma2(wa[4], hv[4], e1);                                          \
        e1 = fma2(wa[6], hv[6], e1);                                          \
        e1 = fma2(wa[8], hv[8], e1);                                          \
        u64 o1 = mul2(wa[1], hv[1]);                                          \
        o1 = fma2(wa[3], hv[3], o1);                                          \
        o1 = fma2(wa[5], hv[5], o1);                                          \
        o1 = fma2(wa[7], hv[7], o1);                                          \
        o1 = fma2(wa[9], hv[9], o1);                                          \
        u64 g1 = add2(e1, o1);                                                \
        u64 e2 = fma2(wb[0], hv[0], bGO);                                     \
        e2 = fma2(wb[2], hv[2], e2);                                          \
        e2 = fma2(wb[4], hv[4], e2);                                          \
        e2 = fma2(wb[6], hv[6], e2);                                          \
        e2 = fma2(wb[8], hv[8], e2);                                          \
        u64 o2 = mul2(wb[1], hv[1]);                                          \
        o2 = fma2(wb[3], hv[3], o2);                                          \
        o2 = fma2(wb[5], hv[5], o2);                                          \
        o2 = fma2(wb[7], hv[7], o2);                                          \
        o2 = fma2(wb[9], hv[9], o2);                                          \
        u64 g2 = add2(e2, o2);                                                \
        if (gemmrole) {                                                       \
            ulonglong2 v; v.x = g1; v.y = g2;                                 \
            (outp)[(size_t)(TT - 1) * HH] = v;                                \
        }                                                                     \
    }

__global__ __launch_bounds__(128) void k_lstm1(
    const float* __restrict__ Whh,    // [40,10] layer-1
    const float* __restrict__ h0,
    const float* __restrict__ c0,
    const float* __restrict__ Wih2,   // [40,10]
    const float* __restrict__ bih2,
    const float* __restrict__ bhh2)
{
    int warp = (blockIdx.x * blockDim.x + threadIdx.x) >> 5;  // 512 warps
    int lane = threadIdx.x & 31;
    int k2 = lane % HH;
    bool gemmrole = (lane >= 10 && lane < 20);
    bool klow = lane < HH;

    const float* Wsel = gemmrole ? Wih2 : Whh;
    u64 wa[10], wb[10];
#pragma unroll
    for (int j = 0; j < 10; j++) {
        wa[j] = pk2(0.25f * Wsel[(0 * HH + k2) * HH + j],
                    0.25f * Wsel[(1 * HH + k2) * HH + j]);
        wb[j] = pk2(0.50f * Wsel[(2 * HH + k2) * HH + j],
                    0.25f * Wsel[(3 * HH + k2) * HH + j]);
    }
    u64 bIF = pk2(0.5f * (bih2[0 * HH + k2] + bhh2[0 * HH + k2]),
                  0.5f * (bih2[1 * HH + k2] + bhh2[1 * HH + k2]));
    u64 bGO = pk2(1.0f * (bih2[2 * HH + k2] + bhh2[2 * HH + k2]),
                  0.5f * (bih2[3 * HH + k2] + bhh2[3 * HH + k2]));

    float hb = 2.0f * h0[warp * HH + k2];
    float cc = c0[warp * HH + k2];
    u64 hv[10];
#pragma unroll
    for (int j = 0; j < 10; j++) {
        float hj = __shfl_sync(0xffffffffu, hb, j);
        hv[j] = pk2(hj, hj);
    }

    const ulonglong2* base =
        reinterpret_cast<const ulonglong2*>(d_XG1) + (size_t)warp * TT * HH + k2;
    ulonglong2* outp =
        reinterpret_cast<ulonglong2*>(d_XG2) + (size_t)warp * TT * HH + k2;

    ulonglong2 cur[4], nxt[4];
#pragma unroll
    for (int i = 0; i < 4; i++) cur[i] = base[i * HH];
#pragma unroll
    for (int i = 0; i < 4; i++) nxt[i] = base[(4 + i) * HH];

    for (int t = 0; t < TT; t += 4) {
        ulonglong2 pf[4];
        if (t + 8 < TT) {
#pragma unroll
            for (int i = 0; i < 4; i++) pf[i] = base[(size_t)(t + 8 + i) * HH];
        }
#pragma unroll
        for (int s = 0; s < 4; s++) {
            STEP1(hb, cc, hv, cur[s], outp, t + s - 1);
        }
#pragma unroll
        for (int i = 0; i < 4; i++) { cur[i] = nxt[i]; nxt[i] = pf[i]; }
    }
    GEMM_TAIL(hv, outp);

    if (klow) {
        d_h1T[warp * HH + k2] = hb;
        d_c1T[warp * HH + k2] = cc;
    }
}

// ---------------------------------------------------------------------------
// lstm2 (exactly R9's proven version): single chain, 4-step unroll, fused FC.
// ---------------------------------------------------------------------------
#define STEP2(hb, cc, hv, ab)                                                 \
    {                                                                         \
        u64 e1 = fma2(wa[0], hv[0], (ab).x);                                  \
        e1 = fma2(wa[2], hv[2], e1);                                          \
        e1 = fma2(wa[4], hv[4], e1);                                          \
        e1 = fma2(wa[6], hv[6], e1);                                          \
        e1 = fma2(wa[8], hv[8], e1);                                          \
        u64 o1 = mul2(wa[1], hv[1]);                                          \
        o1 = fma2(wa[3], hv[3], o1);                                          \
        o1 = fma2(wa[5], hv[5], o1);                                          \
        o1 = fma2(wa[7], hv[7], o1);                                          \
        o1 = fma2(wa[9], hv[9], o1);                                          \
        u64 g1 = add2(e1, o1);                                                \
        u64 e2 = fma2(wb[0], hv[0], (ab).y);                                  \
        e2 = fma2(wb[2], hv[2], e2);                                          \
        e2 = fma2(wb[4], hv[4], e2);                                          \
        e2 = fma2(wb[6], hv[6], e2);                                          \
        e2 = fma2(wb[8], hv[8], e2);                                          \
        u64 o2 = mul2(wb[1], hv[1]);                                          \
        o2 = fma2(wb[3], hv[3], o2);                                          \
        o2 = fma2(wb[5], hv[5], o2);                                          \
        o2 = fma2(wb[7], hv[7], o2);                                          \
        o2 = fma2(wb[9], hv[9], o2);                                          \
        u64 g2 = add2(e2, o2);                                                \
        float xi, xf, xg, xo;                                                 \
        upk2(xi, xf, g1);                                                     \
        upk2(xg, xo, g2);                                                     \
        float ti = tanh_ap(xi);                                               \
        float tf = tanh_ap(xf);                                               \
        float tg = tanh_ap(xg);                                               \
        float to_ = tanh_ap(xo);                                              \
        float u_ = fmaf(tf, cc, cc);                                          \
        float v_ = fmaf(ti, tg, tg);                                          \
        cc = 0.5f * (u_ + v_);                                                \
        float tc = tanh_ap(cc);                                               \
        hb = fmaf(to_, tc, tc);                                               \
        _Pragma("unroll")                                                     \
        for (int j = 0; j < 10; j++) {                                        \
            float hj = __shfl_sync(0xffffffffu, hb, j);                       \
            hv[j] = pk2(hj, hj);                                              \
        }                                                                     \
    }

__global__ __launch_bounds__(128) void k_lstm2(
    const float* __restrict__ Whh,    // [40,10] layer-2
    const float* __restrict__ fc1w,
    const float* __restrict__ fc1b,
    const float* __restrict__ fc2w,   // [1024]
    const float* __restrict__ fc2b,
    float* __restrict__ out)
{
    int warp = (blockIdx.x * blockDim.x + threadIdx.x) >> 5;  // 512 warps
    int lane = threadIdx.x & 31;
    int k2 = lane % HH;
    bool klow = lane < HH;

    u64 wa[10], wb[10];
#pragma unroll
    for (int j = 0; j < 10; j++) {
        wa[j] = pk2(0.25f * Whh[(0 * HH + k2) * HH + j],
                    0.25f * Whh[(1 * HH + k2) * HH + j]);
        wb[j] = pk2(0.50f * Whh[(2 * HH + k2) * HH + j],
                    0.25f * Whh[(3 * HH + k2) * HH + j]);
    }

    float hb = d_h1T[warp * HH + k2];
    float cc = d_c1T[warp * HH + k2];
    u64 hv[10];
#pragma unroll
    for (int j = 0; j < 10; j++) {
        float hj = __shfl_sync(0xffffffffu, hb, j);
        hv[j] = pk2(hj, hj);
    }

    const ulonglong2* base =
        reinterpret_cast<const ulonglong2*>(d_XG2) + (size_t)warp * TT * HH + k2;
    const float4* f4 = reinterpret_cast<const float4*>(fc2w);

    ulonglong2 cur[4], nxt[4];
#pragma unroll
    for (int i = 0; i < 4; i++) cur[i] = base[i * HH];
#pragma unroll
    for (int i = 0; i < 4; i++) nxt[i] = base[(4 + i) * HH];

    float acc = 0.0f;   // sum_t hbig * fc2w[t]
    float s2 = 0.0f;    // sum_t fc2w[t]

    for (int t = 0; t < TT; t += 4) {
        ulonglong2 pf[4];
        if (t + 8 < TT) {
#pragma unroll
            for (int i = 0; i < 4; i++) pf[i] = base[(size_t)(t + 8 + i) * HH];
        }
        float4 fwv = __ldg(&f4[t >> 2]);
        float fw4[4] = {fwv.x, fwv.y, fwv.z, fwv.w};
#pragma unroll
        for (int s = 0; s < 4; s++) {
            STEP2(hb, cc, hv, cur[s]);
            acc = fmaf(hb, fw4[s], acc);
            s2 += fw4[s];
        }
#pragma unroll
        for (int i = 0; i < 4; i++) { cur[i] = nxt[i]; nxt[i] = pf[i]; }
    }

    // acc holds 2*sum(h*fw) -> scale fc1w by 0.5; lanes >=10 contribute 0.
    float val = klow ? acc * (0.5f * fc1w[k2]) : 0.0f;
#pragma unroll
    for (int off = 16; off > 0; off >>= 1)
        val += __shfl_xor_sync(0xffffffffu, val, off);
    if (lane == 0)
        out[warp] = val + fc1b[0] * s2 + fc2b[0];
}

// ---------------------------------------------------------------------------
extern "C" void kernel_launch(void* const* d_in, const int* in_sizes, int n_in,
                              void* d_out, int out_size)
{
    const float* x    = (const float*)d_in[0];
    const float* h0   = (const float*)d_in[1];
    const float* c0   = (const float*)d_in[2];
    const float* Wih1 = (const float*)d_in[3];
    const float* Whh1 = (const float*)d_in[4];
    const float* bih1 = (const float*)d_in[5];
    const float* bhh1 = (const float*)d_in[6];
    const float* Wih2 = (const float*)d_in[7];
    const float* Whh2 = (const float*)d_in[8];
    const float* bih2 = (const float*)d_in[9];
    const float* bhh2 = (const float*)d_in[10];
    const float* fc1w = (const float*)d_in[11];
    const float* fc1b = (const float*)d_in[12];
    const float* fc2w = (const float*)d_in[13];
    const float* fc2b = (const float*)d_in[14];
    float* out = (float*)d_out;

    k_inputgemm<<<1024, 256>>>(x, Wih1, bih1, bhh1);        // 8 rows/thread (98us)
    k_lstm1<<<128, 128>>>(Whh1, h0, c0, Wih2, bih2, bhh2);  // 1 batch/warp, role-shared tree
    k_lstm2<<<128, 128>>>(Whh2, fc1w, fc1b, fc2w, fc2b, out);
}